// round 5
// baseline (speedup 1.0000x reference)
#include <cuda_runtime.h>
#include <cuda_bf16.h>
#include <stdint.h>
#include <math.h>

#define BATCH 4
#define SLEN 2048
#define DDIM 1024
#define NHEAD 16
#define DKH 64
#define MROWS (BATCH * SLEN)  // 8192

// Scratch (alloc-free rule: __device__ globals)
__device__ __nv_bfloat16 g_Qh[MROWS * DDIM];
__device__ __nv_bfloat16 g_Ql[MROWS * DDIM];
__device__ __nv_bfloat16 g_Kh[MROWS * DDIM];
__device__ __nv_bfloat16 g_Kl[MROWS * DDIM];
__device__ __nv_bfloat16 g_Vh[MROWS * DDIM];
__device__ __nv_bfloat16 g_Vl[MROWS * DDIM];
__device__ float g_A[MROWS * DDIM];

// ===================== common helpers =====================
__device__ __forceinline__ uint32_t smem_u32(const void* p) {
    uint32_t a;
    asm("{ .reg .u64 t; cvta.to.shared.u64 t, %1; cvt.u32.u64 %0, t; }"
        : "=r"(a) : "l"(p));
    return a;
}

__device__ __forceinline__ void mma16816(float* c, const uint32_t* a, const uint32_t* b) {
    asm volatile(
        "mma.sync.aligned.m16n8k16.row.col.f32.bf16.bf16.f32 "
        "{%0,%1,%2,%3}, {%4,%5,%6,%7}, {%8,%9}, {%0,%1,%2,%3};"
        : "+f"(c[0]), "+f"(c[1]), "+f"(c[2]), "+f"(c[3])
        : "r"(a[0]), "r"(a[1]), "r"(a[2]), "r"(a[3]), "r"(b[0]), "r"(b[1]));
}

__device__ __forceinline__ uint32_t packbf(float x, float y) {
    uint32_t r;
    asm("cvt.rn.bf16x2.f32 %0, %1, %2;" : "=r"(r) : "f"(y), "f"(x));
    return r;
}
__device__ __forceinline__ void unpackbf(uint32_t w, float& x, float& y) {
    x = __int_as_float(w << 16);
    y = __int_as_float(w & 0xffff0000u);
}

__device__ __forceinline__ void split4(float4 v, uint2& hi, uint2& lo) {
    uint32_t h0 = packbf(v.x, v.y), h1 = packbf(v.z, v.w);
    float a, b, c, d;
    unpackbf(h0, a, b);
    unpackbf(h1, c, d);
    hi.x = h0; hi.y = h1;
    lo.x = packbf(v.x - a, v.y - b);
    lo.y = packbf(v.z - c, v.w - d);
}

// fast exp2 on fma/alu pipes (input <= 0); rel err ~2e-7
__device__ __forceinline__ float fexp2(float t) {
    t = fmaxf(t, -125.f);
    float fi = floorf(t);
    float f = t - fi;
    float p = 1.5353362e-4f;
    p = fmaf(p, f, 1.3398874e-3f);
    p = fmaf(p, f, 9.6184374e-3f);
    p = fmaf(p, f, 5.5503325e-2f);
    p = fmaf(p, f, 2.4022648e-1f);
    p = fmaf(p, f, 6.9314720e-1f);
    p = fmaf(p, f, 1.0f);
    return __int_as_float(__float_as_int(p) + ((int)fi << 23));
}

#define LDSM4(r0, r1, r2, r3, addr)                                            \
    asm volatile("ldmatrix.sync.aligned.m8n8.x4.shared.b16 {%0,%1,%2,%3}, [%4];" \
                 : "=r"(r0), "=r"(r1), "=r"(r2), "=r"(r3) : "r"(addr))
#define LDSM4T(r0, r1, r2, r3, addr)                                           \
    asm volatile("ldmatrix.sync.aligned.m8n8.x4.trans.shared.b16 {%0,%1,%2,%3}, [%4];" \
                 : "=r"(r0), "=r"(r1), "=r"(r2), "=r"(r3) : "r"(addr))

#define CP16(dst, src) \
    asm volatile("cp.async.cg.shared.global [%0], [%1], 16;" :: "r"(dst), "l"(src))
#define CP_COMMIT() asm volatile("cp.async.commit_group;")
#define CP_WAIT(n) asm volatile("cp.async.wait_group %0;" :: "n"(n))

// ===================== GEMM: Y = X @ W^T  (128x64 CTA, 4 warps, 2 CTAs/SM) =====================
#define KC 32
#define NS (DDIM / KC)
#define TSTR 40                      // smem row stride, bf16 elems
#define A_HALF (128 * TSTR)          // elems, one of Ah/Al
#define B_HALF (64 * TSTR)
#define BUF_ELEMS (2 * A_HALF + 2 * B_HALF)
#define GEMM_SMEM (2 * BUF_ELEMS * 2)  // bytes, double buffered (61440)

template <bool SPLIT_OUT>
__device__ __forceinline__ void mma_gemm(const float* __restrict__ X,
                                         const float* __restrict__ W,
                                         float* __restrict__ Yf,
                                         __nv_bfloat16* __restrict__ Yh,
                                         __nv_bfloat16* __restrict__ Yl) {
    extern __shared__ char smem_raw[];
    __nv_bfloat16* smem = (__nv_bfloat16*)smem_raw;

    const int tid = threadIdx.x;
    const int warp = tid >> 5, lane = tid & 31;
    const int wm = warp >> 1;      // 0..1 -> m offset wm*64
    const int wn = warp & 1;       // 0..1 -> n offset wn*32
    const int g = lane >> 2;
    const int tq = lane & 3;
    const int bm = blockIdx.y * 128;
    const int bn = blockIdx.x * 64;

    float acc[4][4][4];
#pragma unroll
    for (int i = 0; i < 4; i++)
#pragma unroll
        for (int j = 0; j < 4; j++)
#pragma unroll
            for (int r = 0; r < 4; r++) acc[i][j][r] = 0.f;

    float4 xr[8], wr[4];

    auto ldg_stage = [&](int s) {
        const int k0 = s * KC;
#pragma unroll
        for (int it = 0; it < 8; it++) {
            int idx = tid + it * 128;
            int row = idx >> 3;
            int c4 = (idx & 7) << 2;
            xr[it] = *(const float4*)(X + (size_t)(bm + row) * DDIM + k0 + c4);
        }
#pragma unroll
        for (int it = 0; it < 4; it++) {
            int idx = tid + it * 128;
            int row = idx >> 3;
            int c4 = (idx & 7) << 2;
            wr[it] = *(const float4*)(W + (size_t)(bn + row) * DDIM + k0 + c4);
        }
    };

    auto sts_stage = [&](int b) {
        __nv_bfloat16* Ah = smem + b * BUF_ELEMS;
        __nv_bfloat16* Al = Ah + A_HALF;
        __nv_bfloat16* Bh = Ah + 2 * A_HALF;
        __nv_bfloat16* Bl = Bh + B_HALF;
#pragma unroll
        for (int it = 0; it < 8; it++) {
            int idx = tid + it * 128;
            int row = idx >> 3;
            int c4 = (idx & 7) << 2;
            int off = row * TSTR + c4;
            uint2 hi, lo;
            split4(xr[it], hi, lo);
            *(uint2*)(Ah + off) = hi;
            *(uint2*)(Al + off) = lo;
        }
#pragma unroll
        for (int it = 0; it < 4; it++) {
            int idx = tid + it * 128;
            int row = idx >> 3;
            int c4 = (idx & 7) << 2;
            int off = row * TSTR + c4;
            uint2 hi, lo;
            split4(wr[it], hi, lo);
            *(uint2*)(Bh + off) = hi;
            *(uint2*)(Bl + off) = lo;
        }
    };

    auto compute = [&](int b) {
        const __nv_bfloat16* Ah = smem + b * BUF_ELEMS;
        const __nv_bfloat16* Al = Ah + A_HALF;
        const __nv_bfloat16* Bh = Ah + 2 * A_HALF;
        const __nv_bfloat16* Bl = Bh + B_HALF;
#pragma unroll
        for (int kk = 0; kk < 2; kk++) {
            const int kb = kk * 16 + tq * 2;
            uint32_t ah[4][4], al[4][4], bh[4][2], bl[4][2];
#pragma unroll
            for (int mt = 0; mt < 4; mt++) {
                const int r0 = wm * 64 + mt * 16 + g;
                ah[mt][0] = *(const uint32_t*)(Ah + r0 * TSTR + kb);
                ah[mt][1] = *(const uint32_t*)(Ah + (r0 + 8) * TSTR + kb);
                ah[mt][2] = *(const uint32_t*)(Ah + r0 * TSTR + kb + 8);
                ah[mt][3] = *(const uint32_t*)(Ah + (r0 + 8) * TSTR + kb + 8);
                al[mt][0] = *(const uint32_t*)(Al + r0 * TSTR + kb);
                al[mt][1] = *(const uint32_t*)(Al + (r0 + 8) * TSTR + kb);
                al[mt][2] = *(const uint32_t*)(Al + r0 * TSTR + kb + 8);
                al[mt][3] = *(const uint32_t*)(Al + (r0 + 8) * TSTR + kb + 8);
            }
#pragma unroll
            for (int nt = 0; nt < 4; nt++) {
                const int n0 = wn * 32 + nt * 8 + g;
                bh[nt][0] = *(const uint32_t*)(Bh + n0 * TSTR + kb);
                bh[nt][1] = *(const uint32_t*)(Bh + n0 * TSTR + kb + 8);
                bl[nt][0] = *(const uint32_t*)(Bl + n0 * TSTR + kb);
                bl[nt][1] = *(const uint32_t*)(Bl + n0 * TSTR + kb + 8);
            }
            // term-major passes: 16 independent MMAs each
#pragma unroll
            for (int mt = 0; mt < 4; mt++)
#pragma unroll
                for (int nt = 0; nt < 4; nt++) mma16816(acc[mt][nt], ah[mt], bh[nt]);
#pragma unroll
            for (int mt = 0; mt < 4; mt++)
#pragma unroll
                for (int nt = 0; nt < 4; nt++) mma16816(acc[mt][nt], ah[mt], bl[nt]);
#pragma unroll
            for (int mt = 0; mt < 4; mt++)
#pragma unroll
                for (int nt = 0; nt < 4; nt++) mma16816(acc[mt][nt], al[mt], bh[nt]);
        }
    };

    ldg_stage(0);
    sts_stage(0);
    __syncthreads();

    for (int s = 0; s < NS; s++) {
        if (s + 1 < NS) ldg_stage(s + 1);
        compute(s & 1);
        if (s + 1 < NS) sts_stage((s + 1) & 1);
        __syncthreads();
    }

#pragma unroll
    for (int mt = 0; mt < 4; mt++) {
        const int row = bm + wm * 64 + mt * 16 + g;
#pragma unroll
        for (int nt = 0; nt < 4; nt++) {
            const int col = bn + wn * 32 + nt * 8 + tq * 2;
            if (SPLIT_OUT) {
                uint32_t* Yh32 = (uint32_t*)Yh;
                uint32_t* Yl32 = (uint32_t*)Yl;
                float a, b;
                uint32_t h0 = packbf(acc[mt][nt][0], acc[mt][nt][1]);
                unpackbf(h0, a, b);
                uint32_t l0 = packbf(acc[mt][nt][0] - a, acc[mt][nt][1] - b);
                Yh32[((size_t)row * DDIM + col) >> 1] = h0;
                Yl32[((size_t)row * DDIM + col) >> 1] = l0;
                uint32_t h1 = packbf(acc[mt][nt][2], acc[mt][nt][3]);
                unpackbf(h1, a, b);
                uint32_t l1 = packbf(acc[mt][nt][2] - a, acc[mt][nt][3] - b);
                Yh32[((size_t)(row + 8) * DDIM + col) >> 1] = h1;
                Yl32[((size_t)(row + 8) * DDIM + col) >> 1] = l1;
            } else {
                *(float2*)(Yf + (size_t)row * DDIM + col) =
                    make_float2(acc[mt][nt][0], acc[mt][nt][1]);
                *(float2*)(Yf + (size_t)(row + 8) * DDIM + col) =
                    make_float2(acc[mt][nt][2], acc[mt][nt][3]);
            }
        }
    }
}

__global__ __launch_bounds__(128, 2) void qkv_mma(const float* __restrict__ X,
                                                  const float* __restrict__ Wq,
                                                  const float* __restrict__ Wk,
                                                  const float* __restrict__ Wv) {
    const float* W = (blockIdx.z == 0) ? Wq : (blockIdx.z == 1) ? Wk : Wv;
    __nv_bfloat16* Yh = (blockIdx.z == 0) ? g_Qh : (blockIdx.z == 1) ? g_Kh : g_Vh;
    __nv_bfloat16* Yl = (blockIdx.z == 0) ? g_Ql : (blockIdx.z == 1) ? g_Kl : g_Vl;
    mma_gemm<true>(X, W, nullptr, Yh, Yl);
}

__global__ __launch_bounds__(128, 2) void oproj_mma(const float* __restrict__ Wo,
                                                    float* __restrict__ out) {
    mma_gemm<false>(g_A, Wo, out, nullptr, nullptr);
}

// ===================== Flash attention (64 q-rows/CTA, 4 warps, 2 CTAs/SM) =====================
#define NT (SLEN / 64)        // 32 kv tiles
#define RSTR 144              // smem row stride bytes: conflict-free LDSM
#define KVARR (64 * RSTR)     // 9216 B
#define KVBUF (4 * KVARR)     // Kh,Kl,Vh,Vl
#define QARR (64 * RSTR)      // 9216 B
#define ATT_SMEM (2 * QARR + 2 * KVBUF)  // 92160 B

__global__ __launch_bounds__(128, 2) void attn_mma() {
    extern __shared__ char smem_raw[];
    const uint32_t smb = smem_u32(smem_raw);
    const uint32_t q_u32 = smb;
    const uint32_t kv_u32 = smb + 2 * QARR;

    const int tid = threadIdx.x;
    const int wm = tid >> 5;       // warp 0..3 -> rows wm*16
    const int lane = tid & 31;
    const int g = lane >> 2;
    const int tq = lane & 3;
    const int mi = lane >> 3;
    const int r8 = lane & 7;
    const int b = blockIdx.y >> 4;
    const int h = blockIdx.y & 15;
    const int q0 = blockIdx.x * 64;
    const size_t bS = (size_t)b * SLEN;
    const int hoff = h * DKH;

    // ---- issue Q loads (group 0): 2 arrays x 64 rows ----
    {
        int arr = tid >> 6, row = tid & 63;
        const __nv_bfloat16* gp =
            (arr ? g_Ql : g_Qh) + (bS + q0 + row) * DDIM + hoff;
        uint32_t dst = q_u32 + arr * QARR + row * RSTR;
#pragma unroll
        for (int i = 0; i < 8; i++) CP16(dst + i * 16, gp + i * 8);
    }
    CP_COMMIT();

    // ---- kv tile loader: 4 arrays x 64 rows, 128 threads -> 2 rows each ----
    auto load_kv = [&](int t, int bb) {
        int arr = tid >> 5;
        int row = tid & 31;
        const __nv_bfloat16* gbase =
            (arr == 0 ? g_Kh : arr == 1 ? g_Kl : arr == 2 ? g_Vh : g_Vl);
        uint32_t dbase = kv_u32 + bb * KVBUF + arr * KVARR;
#pragma unroll
        for (int rr = 0; rr < 2; rr++) {
            const __nv_bfloat16* gp =
                gbase + (bS + t * 64 + row + rr * 32) * DDIM + hoff;
            uint32_t dst = dbase + (row + rr * 32) * RSTR;
#pragma unroll
            for (int i = 0; i < 8; i++) CP16(dst + i * 16, gp + i * 8);
        }
    };

    load_kv(0, 0);
    CP_COMMIT();  // group 1

    float s[8][4];
    float o[8][4];
    float ms0 = -1e30f, ms1 = -1e30f, l0 = 0.f, l1 = 0.f;
#pragma unroll
    for (int j = 0; j < 8; j++)
#pragma unroll
        for (int c = 0; c < 4; c++) o[j][c] = 0.f;
    const float SCL = 0.125f * 1.4426950408889634f;

    // ---- Q fragments (hi/lo) ----
    CP_WAIT(1);
    __syncthreads();
    uint32_t ah[4][4], al[4][4];
#pragma unroll
    for (int kt = 0; kt < 4; kt++) {
        uint32_t addr = q_u32 + (wm * 16 + (mi & 1) * 8 + r8) * RSTR +
                        (kt * 16 + (mi >> 1) * 8) * 2;
        LDSM4(ah[kt][0], ah[kt][1], ah[kt][2], ah[kt][3], addr);
        LDSM4(al[kt][0], al[kt][1], al[kt][2], al[kt][3], addr + QARR);
    }

    for (int t = 0; t < NT; t++) {
        if (t + 1 < NT) {
            load_kv(t + 1, (t + 1) & 1);
            CP_COMMIT();
            CP_WAIT(1);
        } else {
            CP_WAIT(0);
        }
        __syncthreads();

        const uint32_t khb = kv_u32 + (t & 1) * KVBUF;
        const uint32_t vhb = khb + 2 * KVARR;

        // ---- S = Q K^T: per kt, load all K frags, then 3 term-major passes ----
#pragma unroll
        for (int j = 0; j < 8; j++)
#pragma unroll
            for (int c = 0; c < 4; c++) s[j][c] = 0.f;
#pragma unroll
        for (int kt = 0; kt < 4; kt++) {
            uint32_t bh[4][4], bl[4][4];
#pragma unroll
            for (int j2 = 0; j2 < 4; j2++) {
                uint32_t addr = khb + (16 * j2 + (mi >> 1) * 8 + r8) * RSTR +
                                (kt * 16 + (mi & 1) * 8) * 2;
                LDSM4(bh[j2][0], bh[j2][1], bh[j2][2], bh[j2][3], addr);
                LDSM4(bl[j2][0], bl[j2][1], bl[j2][2], bl[j2][3], addr + KVARR);
            }
#pragma unroll
            for (int j2 = 0; j2 < 4; j2++) {
                mma16816(s[2 * j2], ah[kt], bh[j2]);
                mma16816(s[2 * j2 + 1], ah[kt], bh[j2] + 2);
            }
#pragma unroll
            for (int j2 = 0; j2 < 4; j2++) {
                mma16816(s[2 * j2], ah[kt], bl[j2]);
                mma16816(s[2 * j2 + 1], ah[kt], bl[j2] + 2);
            }
#pragma unroll
            for (int j2 = 0; j2 < 4; j2++) {
                mma16816(s[2 * j2], al[kt], bh[j2]);
                mma16816(s[2 * j2 + 1], al[kt], bh[j2] + 2);
            }
        }

        // ---- online softmax ----
        float mx0 = -1e30f, mx1 = -1e30f;
#pragma unroll
        for (int j = 0; j < 8; j++) {
            mx0 = fmaxf(mx0, fmaxf(s[j][0], s[j][1]));
            mx1 = fmaxf(mx1, fmaxf(s[j][2], s[j][3]));
        }
        mx0 = fmaxf(mx0, __shfl_xor_sync(0xffffffffu, mx0, 1));
        mx0 = fmaxf(mx0, __shfl_xor_sync(0xffffffffu, mx0, 2));
        mx1 = fmaxf(mx1, __shfl_xor_sync(0xffffffffu, mx1, 1));
        mx1 = fmaxf(mx1, __shfl_xor_sync(0xffffffffu, mx1, 2));
        float ns0 = fmaxf(ms0, mx0 * SCL);
        float ns1 = fmaxf(ms1, mx1 * SCL);
        float al0 = fexp2(ms0 - ns0);
        float al1 = fexp2(ms1 - ns1);
        ms0 = ns0;
        ms1 = ns1;
        float rs0 = 0.f, rs1 = 0.f;
#pragma unroll
        for (int j = 0; j < 8; j++) {
            float p0 = fexp2(fmaf(s[j][0], SCL, -ns0));
            float p1 = fexp2(fmaf(s[j][1], SCL, -ns0));
            float p2 = fexp2(fmaf(s[j][2], SCL, -ns1));
            float p3 = fexp2(fmaf(s[j][3], SCL, -ns1));
            s[j][0] = p0; s[j][1] = p1; s[j][2] = p2; s[j][3] = p3;
            rs0 += p0 + p1;
            rs1 += p2 + p3;
        }
        rs0 += __shfl_xor_sync(0xffffffffu, rs0, 1);
        rs0 += __shfl_xor_sync(0xffffffffu, rs0, 2);
        rs1 += __shfl_xor_sync(0xffffffffu, rs1, 1);
        rs1 += __shfl_xor_sync(0xffffffffu, rs1, 2);
        l0 = l0 * al0 + rs0;
        l1 = l1 * al1 + rs1;
#pragma unroll
        for (int j = 0; j < 8; j++) {
            o[j][0] *= al0; o[j][1] *= al0;
            o[j][2] *= al1; o[j][3] *= al1;
        }

        // ---- O += P V: per kt, split P, load all V frags, 3 term-major passes ----
#pragma unroll
        for (int kt = 0; kt < 4; kt++) {
            uint32_t aph[4], apl[4];
#pragma unroll
            for (int u = 0; u < 2; u++) {
                const int j = 2 * kt + u;
                uint32_t h0 = packbf(s[j][0], s[j][1]);
                uint32_t h1 = packbf(s[j][2], s[j][3]);
                float a, bb, c, d;
                unpackbf(h0, a, bb);
                unpackbf(h1, c, d);
                aph[2 * u] = h0;
                aph[2 * u + 1] = h1;
                apl[2 * u] = packbf(s[j][0] - a, s[j][1] - bb);
                apl[2 * u + 1] = packbf(s[j][2] - c, s[j][3] - d);
            }
            uint32_t vh[4][4], vl[4][4];
#pragma unroll
            for (int j2 = 0; j2 < 4; j2++) {
                uint32_t addr = vhb + (kt * 16 + (mi & 1) * 8 + r8) * RSTR +
                                (16 * j2 + (mi >> 1) * 8) * 2;
                LDSM4T(vh[j2][0], vh[j2][1], vh[j2][2], vh[j2][3], addr);
                LDSM4T(vl[j2][0], vl[j2][1], vl[j2][2], vl[j2][3], addr + KVARR);
            }
#pragma unroll
            for (int j2 = 0; j2 < 4; j2++) {
                mma16816(o[2 * j2], aph, vh[j2]);
                mma16816(o[2 * j2 + 1], aph, vh[j2] + 2);
            }
#pragma unroll
            for (int j2 = 0; j2 < 4; j2++) {
                mma16816(o[2 * j2], aph, vl[j2]);
                mma16816(o[2 * j2 + 1], aph, vl[j2] + 2);
            }
#pragma unroll
            for (int j2 = 0; j2 < 4; j2++) {
                mma16816(o[2 * j2], apl, vh[j2]);
                mma16816(o[2 * j2 + 1], apl, vh[j2] + 2);
            }
        }
        __syncthreads();
    }

    // ---- epilogue ----
    const float inv0 = 1.f / l0;
    const float inv1 = 1.f / l1;
    const int row0 = q0 + wm * 16 + g;
#pragma unroll
    for (int j = 0; j < 8; j++) {
        const int col = hoff + j * 8 + tq * 2;
        *(float2*)(g_A + (bS + row0) * DDIM + col) =
            make_float2(o[j][0] * inv0, o[j][1] * inv0);
        *(float2*)(g_A + (bS + row0 + 8) * DDIM + col) =
            make_float2(o[j][2] * inv1, o[j][3] * inv1);
    }
}

// ======================= launch =======================
extern "C" void kernel_launch(void* const* d_in, const int* in_sizes, int n_in,
                              void* d_out, int out_size) {
    const float* emb = (const float*)d_in[0];
    const float* Wq  = (const float*)d_in[1];
    const float* Wk  = (const float*)d_in[2];
    const float* Wv  = (const float*)d_in[3];
    const float* Wo  = (const float*)d_in[4];
    float* out = (float*)d_out;

    cudaFuncSetAttribute(qkv_mma, cudaFuncAttributeMaxDynamicSharedMemorySize, GEMM_SMEM);
    cudaFuncSetAttribute(oproj_mma, cudaFuncAttributeMaxDynamicSharedMemorySize, GEMM_SMEM);
    cudaFuncSetAttribute(attn_mma, cudaFuncAttributeMaxDynamicSharedMemorySize, ATT_SMEM);

    dim3 ggrid(DDIM / 64, MROWS / 128, 3);
    qkv_mma<<<ggrid, 128, GEMM_SMEM>>>(emb, Wq, Wk, Wv);

    dim3 agrid(SLEN / 64, BATCH * NHEAD);
    attn_mma<<<agrid, 128, ATT_SMEM>>>();

    dim3 ogrid(DDIM / 64, MROWS / 128, 1);
    oproj_mma<<<ogrid, 128, GEMM_SMEM>>>(Wo, out);
}

// round 6
// speedup vs baseline: 1.1337x; 1.1337x over previous
#include <cuda_runtime.h>
#include <cuda_bf16.h>
#include <stdint.h>
#include <math.h>

#define BATCH 4
#define SLEN 2048
#define DDIM 1024
#define NHEAD 16
#define DKH 64
#define MROWS (BATCH * SLEN)  // 8192

// Scratch (alloc-free rule: __device__ globals)
__device__ __nv_bfloat16 g_Qh[MROWS * DDIM];
__device__ __nv_bfloat16 g_Ql[MROWS * DDIM];
__device__ __nv_bfloat16 g_Kh[MROWS * DDIM];
__device__ __nv_bfloat16 g_Kl[MROWS * DDIM];
__device__ __nv_bfloat16 g_Vh[MROWS * DDIM];
__device__ __nv_bfloat16 g_Vl[MROWS * DDIM];
__device__ float g_A[MROWS * DDIM];

// ===================== common helpers =====================
__device__ __forceinline__ uint32_t smem_u32(const void* p) {
    uint32_t a;
    asm("{ .reg .u64 t; cvta.to.shared.u64 t, %1; cvt.u32.u64 %0, t; }"
        : "=r"(a) : "l"(p));
    return a;
}

__device__ __forceinline__ void mma16816(float* c, const uint32_t* a, const uint32_t* b) {
    asm volatile(
        "mma.sync.aligned.m16n8k16.row.col.f32.bf16.bf16.f32 "
        "{%0,%1,%2,%3}, {%4,%5,%6,%7}, {%8,%9}, {%0,%1,%2,%3};"
        : "+f"(c[0]), "+f"(c[1]), "+f"(c[2]), "+f"(c[3])
        : "r"(a[0]), "r"(a[1]), "r"(a[2]), "r"(a[3]), "r"(b[0]), "r"(b[1]));
}

__device__ __forceinline__ uint32_t packbf(float x, float y) {
    uint32_t r;
    asm("cvt.rn.bf16x2.f32 %0, %1, %2;" : "=r"(r) : "f"(y), "f"(x));
    return r;
}
__device__ __forceinline__ void unpackbf(uint32_t w, float& x, float& y) {
    x = __int_as_float(w << 16);
    y = __int_as_float(w & 0xffff0000u);
}

__device__ __forceinline__ void split4(float4 v, uint2& hi, uint2& lo) {
    uint32_t h0 = packbf(v.x, v.y), h1 = packbf(v.z, v.w);
    float a, b, c, d;
    unpackbf(h0, a, b);
    unpackbf(h1, c, d);
    hi.x = h0; hi.y = h1;
    lo.x = packbf(v.x - a, v.y - b);
    lo.y = packbf(v.z - c, v.w - d);
}

// fast exp2 on fma/alu pipes (input <= 0); rel err ~2e-7
__device__ __forceinline__ float fexp2(float t) {
    t = fmaxf(t, -125.f);
    float fi = floorf(t);
    float f = t - fi;
    float p = 1.5353362e-4f;
    p = fmaf(p, f, 1.3398874e-3f);
    p = fmaf(p, f, 9.6184374e-3f);
    p = fmaf(p, f, 5.5503325e-2f);
    p = fmaf(p, f, 2.4022648e-1f);
    p = fmaf(p, f, 6.9314720e-1f);
    p = fmaf(p, f, 1.0f);
    return __int_as_float(__float_as_int(p) + ((int)fi << 23));
}

#define LDSM4(r0, r1, r2, r3, addr)                                            \
    asm volatile("ldmatrix.sync.aligned.m8n8.x4.shared.b16 {%0,%1,%2,%3}, [%4];" \
                 : "=r"(r0), "=r"(r1), "=r"(r2), "=r"(r3) : "r"(addr))
#define LDSM4T(r0, r1, r2, r3, addr)                                           \
    asm volatile("ldmatrix.sync.aligned.m8n8.x4.trans.shared.b16 {%0,%1,%2,%3}, [%4];" \
                 : "=r"(r0), "=r"(r1), "=r"(r2), "=r"(r3) : "r"(addr))

#define CP16(dst, src) \
    asm volatile("cp.async.cg.shared.global [%0], [%1], 16;" :: "r"(dst), "l"(src))
#define CP_COMMIT() asm volatile("cp.async.commit_group;")
#define CP_WAIT(n) asm volatile("cp.async.wait_group %0;" :: "n"(n))

// ===================== GEMM: Y = X @ W^T  (128x128 CTA, 8 warps, ldmatrix frags) ===========
#define KC 32
#define NS (DDIM / KC)
#define TSTR 40                       // smem row stride, bf16 elems (80 B)
#define ROWB 80                       // bytes per row
#define HALF_B (128 * ROWB)           // 10240 B: one of Ah/Al/Bh/Bl
#define BUF_B (4 * HALF_B)            // 40960 B per stage
#define GEMM_SMEM (2 * BUF_B)         // 81920 B double buffered

template <bool SPLIT_OUT>
__device__ __forceinline__ void mma_gemm(const float* __restrict__ X,
                                         const float* __restrict__ W,
                                         float* __restrict__ Yf,
                                         __nv_bfloat16* __restrict__ Yh,
                                         __nv_bfloat16* __restrict__ Yl) {
    extern __shared__ char smem_raw[];
    __nv_bfloat16* smem = (__nv_bfloat16*)smem_raw;
    const uint32_t smb = smem_u32(smem_raw);

    const int tid = threadIdx.x;
    const int warp = tid >> 5, lane = tid & 31;
    const int wm = warp >> 2;      // 0..1 -> m offset wm*64
    const int wn = warp & 3;       // 0..3 -> n offset wn*32
    const int g = lane >> 2;
    const int tq = lane & 3;
    const int mi = lane >> 3;      // ldmatrix matrix index 0..3
    const int r8 = lane & 7;
    const int bm = blockIdx.y * 128;
    const int bn = blockIdx.x * 128;

    float acc[4][4][4];
#pragma unroll
    for (int i = 0; i < 4; i++)
#pragma unroll
        for (int j = 0; j < 4; j++)
#pragma unroll
            for (int r = 0; r < 4; r++) acc[i][j][r] = 0.f;

    float4 xr[4], wr[4];

    auto ldg_stage = [&](int s) {
        const int k0 = s * KC;
#pragma unroll
        for (int it = 0; it < 4; it++) {
            int idx = tid + it * 256;
            int row = idx >> 3;
            int c4 = (idx & 7) << 2;
            xr[it] = *(const float4*)(X + (size_t)(bm + row) * DDIM + k0 + c4);
            wr[it] = *(const float4*)(W + (size_t)(bn + row) * DDIM + k0 + c4);
        }
    };

    auto sts_stage = [&](int b) {
        __nv_bfloat16* Ah = smem + b * (BUF_B / 2);   // elems offset = bytes/2
        __nv_bfloat16* Al = Ah + HALF_B / 2;
        __nv_bfloat16* Bh = Ah + 2 * (HALF_B / 2);
        __nv_bfloat16* Bl = Ah + 3 * (HALF_B / 2);
#pragma unroll
        for (int it = 0; it < 4; it++) {
            int idx = tid + it * 256;
            int row = idx >> 3;
            int c4 = (idx & 7) << 2;
            int off = row * TSTR + c4;
            uint2 hi, lo;
            split4(xr[it], hi, lo);
            *(uint2*)(Ah + off) = hi;
            *(uint2*)(Al + off) = lo;
            split4(wr[it], hi, lo);
            *(uint2*)(Bh + off) = hi;
            *(uint2*)(Bl + off) = lo;
        }
    };

    // ldmatrix-based fragment loads + term-major MMA passes
    auto compute = [&](int b) {
        const uint32_t Ah = smb + b * BUF_B;
        const uint32_t Bh = Ah + 2 * HALF_B;
#pragma unroll
        for (int kt = 0; kt < 2; kt++) {
            uint32_t ah[4][4], al[4][4], bh[2][4], bl[2][4];
#pragma unroll
            for (int mt = 0; mt < 4; mt++) {
                // A frag order {m0k0, m8k0, m0k8, m8k8}: (mi&1)->row+8, (mi>>1)->col+8
                uint32_t ar = Ah + (wm * 64 + mt * 16 + (mi & 1) * 8 + r8) * ROWB +
                              (kt * 16 + (mi >> 1) * 8) * 2;
                LDSM4(ah[mt][0], ah[mt][1], ah[mt][2], ah[mt][3], ar);
                LDSM4(al[mt][0], al[mt][1], al[mt][2], al[mt][3], ar + HALF_B);
            }
#pragma unroll
            for (int j = 0; j < 2; j++) {
                // B frag order {n0k0, n0k8, n8k0, n8k8}: (mi>>1)->row+8, (mi&1)->col+8
                uint32_t br = Bh + (wn * 32 + j * 16 + (mi >> 1) * 8 + r8) * ROWB +
                              (kt * 16 + (mi & 1) * 8) * 2;
                LDSM4(bh[j][0], bh[j][1], bh[j][2], bh[j][3], br);
                LDSM4(bl[j][0], bl[j][1], bl[j][2], bl[j][3], br + HALF_B);
            }
            // term-major passes: 16 independent MMAs each
#pragma unroll
            for (int mt = 0; mt < 4; mt++)
#pragma unroll
                for (int j = 0; j < 2; j++)
#pragma unroll
                    for (int h = 0; h < 2; h++)
                        mma16816(acc[mt][2 * j + h], ah[mt], bh[j] + 2 * h);
#pragma unroll
            for (int mt = 0; mt < 4; mt++)
#pragma unroll
                for (int j = 0; j < 2; j++)
#pragma unroll
                    for (int h = 0; h < 2; h++)
                        mma16816(acc[mt][2 * j + h], ah[mt], bl[j] + 2 * h);
#pragma unroll
            for (int mt = 0; mt < 4; mt++)
#pragma unroll
                for (int j = 0; j < 2; j++)
#pragma unroll
                    for (int h = 0; h < 2; h++)
                        mma16816(acc[mt][2 * j + h], al[mt], bh[j] + 2 * h);
        }
    };

    ldg_stage(0);
    sts_stage(0);
    __syncthreads();

    for (int s = 0; s < NS; s++) {
        if (s + 1 < NS) ldg_stage(s + 1);
        compute(s & 1);
        if (s + 1 < NS) sts_stage((s + 1) & 1);
        __syncthreads();
    }

#pragma unroll
    for (int mt = 0; mt < 4; mt++) {
        const int row = bm + wm * 64 + mt * 16 + g;
#pragma unroll
        for (int nt = 0; nt < 4; nt++) {
            const int col = bn + wn * 32 + nt * 8 + tq * 2;
            if (SPLIT_OUT) {
                uint32_t* Yh32 = (uint32_t*)Yh;
                uint32_t* Yl32 = (uint32_t*)Yl;
                float a, b;
                uint32_t h0 = packbf(acc[mt][nt][0], acc[mt][nt][1]);
                unpackbf(h0, a, b);
                uint32_t l0 = packbf(acc[mt][nt][0] - a, acc[mt][nt][1] - b);
                Yh32[((size_t)row * DDIM + col) >> 1] = h0;
                Yl32[((size_t)row * DDIM + col) >> 1] = l0;
                uint32_t h1 = packbf(acc[mt][nt][2], acc[mt][nt][3]);
                unpackbf(h1, a, b);
                uint32_t l1 = packbf(acc[mt][nt][2] - a, acc[mt][nt][3] - b);
                Yh32[((size_t)(row + 8) * DDIM + col) >> 1] = h1;
                Yl32[((size_t)(row + 8) * DDIM + col) >> 1] = l1;
            } else {
                *(float2*)(Yf + (size_t)row * DDIM + col) =
                    make_float2(acc[mt][nt][0], acc[mt][nt][1]);
                *(float2*)(Yf + (size_t)(row + 8) * DDIM + col) =
                    make_float2(acc[mt][nt][2], acc[mt][nt][3]);
            }
        }
    }
}

__global__ __launch_bounds__(256, 1) void qkv_mma(const float* __restrict__ X,
                                                  const float* __restrict__ Wq,
                                                  const float* __restrict__ Wk,
                                                  const float* __restrict__ Wv) {
    const float* W = (blockIdx.z == 0) ? Wq : (blockIdx.z == 1) ? Wk : Wv;
    __nv_bfloat16* Yh = (blockIdx.z == 0) ? g_Qh : (blockIdx.z == 1) ? g_Kh : g_Vh;
    __nv_bfloat16* Yl = (blockIdx.z == 0) ? g_Ql : (blockIdx.z == 1) ? g_Kl : g_Vl;
    mma_gemm<true>(X, W, nullptr, Yh, Yl);
}

__global__ __launch_bounds__(256, 1) void oproj_mma(const float* __restrict__ Wo,
                                                    float* __restrict__ out) {
    mma_gemm<false>(g_A, Wo, out, nullptr, nullptr);
}

// ===================== Flash attention: 256 q-rows/CTA, 8 warps x 32 rows =====================
#define NT (SLEN / 64)        // 32 kv tiles
#define RSTR 144              // smem row stride bytes: conflict-free LDSM
#define KVARR (64 * RSTR)     // 9216 B
#define KVBUF (4 * KVARR)     // Kh,Kl,Vh,Vl
#define QARR (256 * RSTR)     // 36864 B
#define ATT_SMEM (2 * QARR + 2 * KVBUF)  // 147456 B

__global__ __launch_bounds__(256, 1) void attn_mma() {
    extern __shared__ char smem_raw[];
    const uint32_t smb = smem_u32(smem_raw);
    const uint32_t q_u32 = smb;
    const uint32_t kv_u32 = smb + 2 * QARR;

    const int tid = threadIdx.x;
    const int wm = tid >> 5;       // warp 0..7 -> rows wm*32
    const int lane = tid & 31;
    const int g = lane >> 2;
    const int tq = lane & 3;
    const int mi = lane >> 3;
    const int r8 = lane & 7;
    const int b = blockIdx.y >> 4;
    const int h = blockIdx.y & 15;
    const int q0 = blockIdx.x * 256;
    const size_t bS = (size_t)b * SLEN;
    const int hoff = h * DKH;

    // ---- issue Q loads (group 0): 2 arrays x 256 rows, 2 per thread ----
#pragma unroll
    for (int p = 0; p < 2; p++) {
        int task = tid + p * 256;
        int arr = task >> 8, row = task & 255;
        const __nv_bfloat16* gp =
            (arr ? g_Ql : g_Qh) + (bS + q0 + row) * DDIM + hoff;
        uint32_t dst = q_u32 + arr * QARR + row * RSTR;
#pragma unroll
        for (int i = 0; i < 8; i++) CP16(dst + i * 16, gp + i * 8);
    }
    CP_COMMIT();

    // ---- kv tile loader: 4 arrays x 64 rows, 1 row per thread ----
    auto load_kv = [&](int t, int bb) {
        int arr = tid >> 6, row = tid & 63;
        const __nv_bfloat16* gp =
            (arr == 0 ? g_Kh : arr == 1 ? g_Kl : arr == 2 ? g_Vh : g_Vl) +
            (bS + t * 64 + row) * DDIM + hoff;
        uint32_t dst = kv_u32 + bb * KVBUF + arr * KVARR + row * RSTR;
#pragma unroll
        for (int i = 0; i < 8; i++) CP16(dst + i * 16, gp + i * 8);
    };

    load_kv(0, 0);
    CP_COMMIT();  // group 1

    // per-warp state: 2 m-tiles of 16 rows; stats idx = mt*2 + rowhalf
    float s[2][8][4];
    float o[2][8][4];
    float ms[4] = {-1e30f, -1e30f, -1e30f, -1e30f};
    float l[4] = {0.f, 0.f, 0.f, 0.f};
#pragma unroll
    for (int mt = 0; mt < 2; mt++)
#pragma unroll
        for (int j = 0; j < 8; j++)
#pragma unroll
            for (int c = 0; c < 4; c++) o[mt][j][c] = 0.f;
    const float SCL = 0.125f * 1.4426950408889634f;

    CP_WAIT(1);  // Q resident
    __syncthreads();

    for (int t = 0; t < NT; t++) {
        if (t + 1 < NT) {
            load_kv(t + 1, (t + 1) & 1);
            CP_COMMIT();
            CP_WAIT(1);
        } else {
            CP_WAIT(0);
        }
        __syncthreads();

        const uint32_t khb = kv_u32 + (t & 1) * KVBUF;
        const uint32_t vhb = khb + 2 * KVARR;

        // ---- S = Q K^T (Q frags re-loaded from smem; 3 term-major passes) ----
#pragma unroll
        for (int mt = 0; mt < 2; mt++)
#pragma unroll
            for (int j = 0; j < 8; j++)
#pragma unroll
                for (int c = 0; c < 4; c++) s[mt][j][c] = 0.f;
#pragma unroll
        for (int kt = 0; kt < 4; kt++) {
            uint32_t bh[4][4], bl[4][4];
#pragma unroll
            for (int j2 = 0; j2 < 4; j2++) {
                uint32_t addr = khb + (16 * j2 + (mi >> 1) * 8 + r8) * RSTR +
                                (kt * 16 + (mi & 1) * 8) * 2;
                LDSM4(bh[j2][0], bh[j2][1], bh[j2][2], bh[j2][3], addr);
                LDSM4(bl[j2][0], bl[j2][1], bl[j2][2], bl[j2][3], addr + KVARR);
            }
#pragma unroll
            for (int mt = 0; mt < 2; mt++) {
                uint32_t qaddr = q_u32 + (wm * 32 + mt * 16 + (mi & 1) * 8 + r8) * RSTR +
                                 (kt * 16 + (mi >> 1) * 8) * 2;
                uint32_t ah[4], al[4];
                LDSM4(ah[0], ah[1], ah[2], ah[3], qaddr);
                LDSM4(al[0], al[1], al[2], al[3], qaddr + QARR);
#pragma unroll
                for (int j2 = 0; j2 < 4; j2++) {
                    mma16816(s[mt][2 * j2], ah, bh[j2]);
                    mma16816(s[mt][2 * j2 + 1], ah, bh[j2] + 2);
                }
#pragma unroll
                for (int j2 = 0; j2 < 4; j2++) {
                    mma16816(s[mt][2 * j2], ah, bl[j2]);
                    mma16816(s[mt][2 * j2 + 1], ah, bl[j2] + 2);
                }
#pragma unroll
                for (int j2 = 0; j2 < 4; j2++) {
                    mma16816(s[mt][2 * j2], al, bh[j2]);
                    mma16816(s[mt][2 * j2 + 1], al, bh[j2] + 2);
                }
            }
        }

        // ---- online softmax (per mt, per row-half) ----
#pragma unroll
        for (int mt = 0; mt < 2; mt++) {
            float mx0 = -1e30f, mx1 = -1e30f;
#pragma unroll
            for (int j = 0; j < 8; j++) {
                mx0 = fmaxf(mx0, fmaxf(s[mt][j][0], s[mt][j][1]));
                mx1 = fmaxf(mx1, fmaxf(s[mt][j][2], s[mt][j][3]));
            }
            mx0 = fmaxf(mx0, __shfl_xor_sync(0xffffffffu, mx0, 1));
            mx0 = fmaxf(mx0, __shfl_xor_sync(0xffffffffu, mx0, 2));
            mx1 = fmaxf(mx1, __shfl_xor_sync(0xffffffffu, mx1, 1));
            mx1 = fmaxf(mx1, __shfl_xor_sync(0xffffffffu, mx1, 2));
            float ns0 = fmaxf(ms[2 * mt], mx0 * SCL);
            float ns1 = fmaxf(ms[2 * mt + 1], mx1 * SCL);
            float al0 = fexp2(ms[2 * mt] - ns0);
            float al1 = fexp2(ms[2 * mt + 1] - ns1);
            ms[2 * mt] = ns0;
            ms[2 * mt + 1] = ns1;
            float rs0 = 0.f, rs1 = 0.f;
#pragma unroll
            for (int j = 0; j < 8; j++) {
                float p0 = fexp2(fmaf(s[mt][j][0], SCL, -ns0));
                float p1 = fexp2(fmaf(s[mt][j][1], SCL, -ns0));
                float p2 = fexp2(fmaf(s[mt][j][2], SCL, -ns1));
                float p3 = fexp2(fmaf(s[mt][j][3], SCL, -ns1));
                s[mt][j][0] = p0; s[mt][j][1] = p1;
                s[mt][j][2] = p2; s[mt][j][3] = p3;
                rs0 += p0 + p1;
                rs1 += p2 + p3;
            }
            rs0 += __shfl_xor_sync(0xffffffffu, rs0, 1);
            rs0 += __shfl_xor_sync(0xffffffffu, rs0, 2);
            rs1 += __shfl_xor_sync(0xffffffffu, rs1, 1);
            rs1 += __shfl_xor_sync(0xffffffffu, rs1, 2);
            l[2 * mt] = l[2 * mt] * al0 + rs0;
            l[2 * mt + 1] = l[2 * mt + 1] * al1 + rs1;
#pragma unroll
            for (int j = 0; j < 8; j++) {
                o[mt][j][0] *= al0; o[mt][j][1] *= al0;
                o[mt][j][2] *= al1; o[mt][j][3] *= al1;
            }
        }

        // ---- O += P V (split P per mt; V frags shared across mt) ----
#pragma unroll
        for (int kt = 0; kt < 4; kt++) {
            uint32_t vh[4][4], vl[4][4];
#pragma unroll
            for (int j2 = 0; j2 < 4; j2++) {
                uint32_t addr = vhb + (kt * 16 + (mi & 1) * 8 + r8) * RSTR +
                                (16 * j2 + (mi >> 1) * 8) * 2;
                LDSM4T(vh[j2][0], vh[j2][1], vh[j2][2], vh[j2][3], addr);
                LDSM4T(vl[j2][0], vl[j2][1], vl[j2][2], vl[j2][3], addr + KVARR);
            }
#pragma unroll
            for (int mt = 0; mt < 2; mt++) {
                uint32_t aph[4], apl[4];
#pragma unroll
                for (int u = 0; u < 2; u++) {
                    const int j = 2 * kt + u;
                    uint32_t h0 = packbf(s[mt][j][0], s[mt][j][1]);
                    uint32_t h1 = packbf(s[mt][j][2], s[mt][j][3]);
                    float a, bb, c, d;
                    unpackbf(h0, a, bb);
                    unpackbf(h1, c, d);
                    aph[2 * u] = h0;
                    aph[2 * u + 1] = h1;
                    apl[2 * u] = packbf(s[mt][j][0] - a, s[mt][j][1] - bb);
                    apl[2 * u + 1] = packbf(s[mt][j][2] - c, s[mt][j][3] - d);
                }
#pragma unroll
                for (int j2 = 0; j2 < 4; j2++) {
                    mma16816(o[mt][2 * j2], aph, vh[j2]);
                    mma16816(o[mt][2 * j2 + 1], aph, vh[j2] + 2);
                }
#pragma unroll
                for (int j2 = 0; j2 < 4; j2++) {
                    mma16816(o[mt][2 * j2], aph, vl[j2]);
                    mma16816(o[mt][2 * j2 + 1], aph, vl[j2] + 2);
                }
#pragma unroll
                for (int j2 = 0; j2 < 4; j2++) {
                    mma16816(o[mt][2 * j2], apl, vh[j2]);
                    mma16816(o[mt][2 * j2 + 1], apl, vh[j2] + 2);
                }
            }
        }
        __syncthreads();
    }

    // ---- epilogue ----
#pragma unroll
    for (int mt = 0; mt < 2; mt++) {
        const float inv0 = 1.f / l[2 * mt];
        const float inv1 = 1.f / l[2 * mt + 1];
        const int row0 = q0 + wm * 32 + mt * 16 + g;
#pragma unroll
        for (int j = 0; j < 8; j++) {
            const int col = hoff + j * 8 + tq * 2;
            *(float2*)(g_A + (bS + row0) * DDIM + col) =
                make_float2(o[mt][j][0] * inv0, o[mt][j][1] * inv0);
            *(float2*)(g_A + (bS + row0 + 8) * DDIM + col) =
                make_float2(o[mt][j][2] * inv1, o[mt][j][3] * inv1);
        }
    }
}

// ======================= launch =======================
extern "C" void kernel_launch(void* const* d_in, const int* in_sizes, int n_in,
                              void* d_out, int out_size) {
    const float* emb = (const float*)d_in[0];
    const float* Wq  = (const float*)d_in[1];
    const float* Wk  = (const float*)d_in[2];
    const float* Wv  = (const float*)d_in[3];
    const float* Wo  = (const float*)d_in[4];
    float* out = (float*)d_out;

    cudaFuncSetAttribute(qkv_mma, cudaFuncAttributeMaxDynamicSharedMemorySize, GEMM_SMEM);
    cudaFuncSetAttribute(oproj_mma, cudaFuncAttributeMaxDynamicSharedMemorySize, GEMM_SMEM);
    cudaFuncSetAttribute(attn_mma, cudaFuncAttributeMaxDynamicSharedMemorySize, ATT_SMEM);

    dim3 ggrid(DDIM / 128, MROWS / 128, 3);
    qkv_mma<<<ggrid, 256, GEMM_SMEM>>>(emb, Wq, Wk, Wv);

    dim3 agrid(SLEN / 256, BATCH * NHEAD);
    attn_mma<<<agrid, 256, ATT_SMEM>>>();

    dim3 ogrid(DDIM / 128, MROWS / 128, 1);
    oproj_mma<<<ogrid, 256, GEMM_SMEM>>>(Wo, out);
}